// round 2
// baseline (speedup 1.0000x reference)
#include <cuda_runtime.h>
#include <math.h>
#include <stdint.h>
#include <stddef.h>

// ---------------------------------------------------------------------------
// SpeechTopKDecoder: T=64-step beam-search decoder. fp32 throughout.
// Deterministic: fixed-order split-K reductions, no float atomics.
// All scratch in __device__ globals (no allocation anywhere).
// ---------------------------------------------------------------------------

#define Bb   16
#define Kb   3
#define Sx   512
#define Hx   1024
#define Cx   2000
#define Tx   64
#define NHx  4
#define DHx  256
#define BKx  48
#define NEGV (-1000000000.0f)
#define SOSv 1
#define EOSv 2

#define SPL 8    // lstm split-K (per 1024-K pair)
#define SPQ 16   // q / p split-K
#define SPG 8    // wg split-K

// ------------------------------ device scratch ------------------------------
__device__ float g_kT [(size_t)Bb * NHx * DHx * Sx];   // keys   (B,NH,DH,S)
__device__ float g_vv [(size_t)Bb * NHx * Sx * DHx];   // values (B,NH,S,DH)
__device__ float g_h  [2 * BKx * Hx];                  // gathered h (cur)
__device__ float g_c  [2 * BKx * Hx];                  // gathered c (cur)
__device__ float g_hs [2 * BKx * Hx];                  // staged new h
__device__ float g_cs [2 * BKx * Hx];                  // staged new c
__device__ float g_gatesP[(size_t)SPL * BKx * 4096];   // lstm partials
__device__ float g_qP [(size_t)SPQ * BKx * Hx];        // q partials
__device__ float g_pP [(size_t)SPQ * BKx * Hx];        // p partials
__device__ float g_gP [(size_t)SPG * BKx * 2048];      // wg partials (padded N)
__device__ float g_ctx [BKx * Hx];
__device__ float g_out1[BKx * Hx];
__device__ float g_tanh[BKx * Hx];
__device__ float g_cand[BKx * Cx];
__device__ float g_score[BKx];
__device__ int   g_inp [BKx];
__device__ int   g_pred[BKx];

// ------------------------------ reductions ----------------------------------
__device__ __forceinline__ float warpMax(float v) {
#pragma unroll
    for (int o = 16; o; o >>= 1) v = fmaxf(v, __shfl_xor_sync(0xffffffffu, v, o));
    return v;
}
__device__ __forceinline__ float warpSum(float v) {
#pragma unroll
    for (int o = 16; o; o >>= 1) v += __shfl_xor_sync(0xffffffffu, v, o);
    return v;
}
// 256-thread block reductions (deterministic order), red[8] scratch
__device__ __forceinline__ float blockMax(float v, float* red, int tid) {
    v = warpMax(v);
    if ((tid & 31) == 0) red[tid >> 5] = v;
    __syncthreads();
    float r = red[0];
#pragma unroll
    for (int w = 1; w < 8; w++) r = fmaxf(r, red[w]);
    __syncthreads();
    return r;
}
__device__ __forceinline__ float blockSum(float v, float* red, int tid) {
    v = warpSum(v);
    if ((tid & 31) == 0) red[tid >> 5] = v;
    __syncthreads();
    float r = red[0];
#pragma unroll
    for (int w = 1; w < 8; w++) r += red[w];
    __syncthreads();
    return r;
}
__device__ __forceinline__ float sigf(float x) { return 1.0f / (1.0f + expf(-x)); }

// ------------------------------ init ----------------------------------------
__global__ void init_kernel() {
    int idx = blockIdx.x * 256 + threadIdx.x;
    if (idx < 2 * BKx * Hx) { g_h[idx] = 0.0f; g_c[idx] = 0.0f; }
    if (idx < BKx) {
        g_score[idx] = (idx % Kb == 0) ? 0.0f : NEGV;
        g_inp[idx] = SOSv;
    }
}

// ------------------------------ K/V projection ------------------------------
// grid (16 n-tiles, 128 m-tiles, 2 {k,v}), 256 threads. 64x64 tiles, K=1024.
__global__ void kvproj_kernel(const float* __restrict__ enc,
                              const float* __restrict__ wk_, const float* __restrict__ bk_,
                              const float* __restrict__ wv_, const float* __restrict__ bv_) {
    const int z = blockIdx.z;
    const float* W    = z ? wv_ : wk_;
    const float* bias = z ? bv_ : bk_;
    const int n0 = blockIdx.x * 64;
    const int m0 = blockIdx.y * 64;
    const int b  = m0 >> 9;
    const int s0 = m0 & 511;

    __shared__ float As[16][68];
    __shared__ float Bs[16][64];
    const int tid = threadIdx.x;
    const int tx = tid & 15, ty = tid >> 4;

    float acc[4][4];
#pragma unroll
    for (int i = 0; i < 4; i++)
#pragma unroll
        for (int j = 0; j < 4; j++) acc[i][j] = 0.0f;

    for (int kb = 0; kb < Hx; kb += 16) {
#pragma unroll
        for (int i = tid; i < 64 * 16; i += 256) {
            int m = i >> 4, kk = i & 15;
            As[kk][m] = enc[(size_t)(m0 + m) * Hx + kb + kk];
        }
#pragma unroll
        for (int i = tid; i < 16 * 16; i += 256) {
            int kk = i >> 4, n4 = i & 15;
            *(float4*)&Bs[kk][n4 * 4] = *(const float4*)(W + (size_t)(kb + kk) * Hx + n0 + n4 * 4);
        }
        __syncthreads();
#pragma unroll
        for (int kk = 0; kk < 16; kk++) {
            float4 a = *(const float4*)&As[kk][ty * 4];
            float4 bb = *(const float4*)&Bs[kk][tx * 4];
            float av[4] = {a.x, a.y, a.z, a.w};
            float bvv[4] = {bb.x, bb.y, bb.z, bb.w};
#pragma unroll
            for (int i = 0; i < 4; i++)
#pragma unroll
                for (int j = 0; j < 4; j++) acc[i][j] += av[i] * bvv[j];
        }
        __syncthreads();
    }
#pragma unroll
    for (int i = 0; i < 4; i++) {
        int s = s0 + ty * 4 + i;
#pragma unroll
        for (int j = 0; j < 4; j++) {
            int col = n0 + tx * 4 + j;
            int h = col >> 8, d = col & 255;
            float v = acc[i][j] + bias[col];
            if (z == 0)
                g_kT[(((size_t)b * NHx + h) * DHx + d) * Sx + s] = v;
            else
                g_vv[(((size_t)b * NHx + h) * Sx + s) * DHx + d] = v;
        }
    }
}

// ------------------------------ generic 48-row GEMM -------------------------
// C_part[sp][48][Nstride] (+)= A(48,K-slice) * B.  BT: B is (N,K) row-major
// (use B[n][k]); else B is (K,N) with row stride N (use B[k][n]).
// Optional second pair (A1,B1) accumulates into the same partial (lstm).
// Optional row-gather for A0 (embedding lookup).
template <bool BT>
__global__ void __launch_bounds__(256)
gemm48(const float* __restrict__ A0, const int* __restrict__ aidx,
       const float* __restrict__ B0,
       const float* __restrict__ A1, const float* __restrict__ B1,
       int K, int kPerSplit, int N, int Nstride,
       float* __restrict__ Cpart) {
    __shared__ float As[32][49];
    __shared__ float Bs[32][132];
    __shared__ int sIdx[48];

    const int tid = threadIdx.x;
    const int tx = tid & 15, ty = tid >> 4;
    const int n0 = blockIdx.x * 128;
    const int sp = blockIdx.y;
    const int k0 = sp * kPerSplit;

    if (aidx != nullptr && tid < 48) sIdx[tid] = aidx[tid];
    __syncthreads();

    float acc[3][8];
#pragma unroll
    for (int i = 0; i < 3; i++)
#pragma unroll
        for (int j = 0; j < 8; j++) acc[i][j] = 0.0f;

#pragma unroll 1
    for (int pair = 0; pair < 2; pair++) {
        const float* A = pair ? A1 : A0;
        const float* B = pair ? B1 : B0;
        if (A == nullptr) break;
        const bool gat = (pair == 0) && (aidx != nullptr);
#pragma unroll 1
        for (int kb = k0; kb < k0 + kPerSplit; kb += 32) {
#pragma unroll
            for (int i = tid; i < 48 * 32; i += 256) {
                int m = i >> 5, kk = i & 31;
                const float* Arow = A + (size_t)(gat ? sIdx[m] : m) * K;
                As[kk][m] = Arow[kb + kk];
            }
            if (BT) {
#pragma unroll
                for (int i = tid; i < 128 * 8; i += 256) {
                    int n = i >> 3, k4 = i & 7;
                    float4 v = *(const float4*)(B + (size_t)(n0 + n) * K + kb + k4 * 4);
                    Bs[k4 * 4 + 0][n] = v.x; Bs[k4 * 4 + 1][n] = v.y;
                    Bs[k4 * 4 + 2][n] = v.z; Bs[k4 * 4 + 3][n] = v.w;
                }
            } else {
#pragma unroll
                for (int i = tid; i < 32 * 32; i += 256) {
                    int kk = i >> 5, n4 = i & 31;
                    int col = n0 + n4 * 4;
                    float4 v = make_float4(0.f, 0.f, 0.f, 0.f);
                    if (col < N) v = *(const float4*)(B + (size_t)(kb + kk) * N + col);
                    *(float4*)&Bs[kk][n4 * 4] = v;
                }
            }
            __syncthreads();
#pragma unroll
            for (int kk = 0; kk < 32; kk++) {
                float a0 = As[kk][ty * 3 + 0];
                float a1 = As[kk][ty * 3 + 1];
                float a2 = As[kk][ty * 3 + 2];
                float4 b0 = *(const float4*)&Bs[kk][tx * 8];
                float4 b1 = *(const float4*)&Bs[kk][tx * 8 + 4];
                acc[0][0] += a0 * b0.x; acc[0][1] += a0 * b0.y; acc[0][2] += a0 * b0.z; acc[0][3] += a0 * b0.w;
                acc[0][4] += a0 * b1.x; acc[0][5] += a0 * b1.y; acc[0][6] += a0 * b1.z; acc[0][7] += a0 * b1.w;
                acc[1][0] += a1 * b0.x; acc[1][1] += a1 * b0.y; acc[1][2] += a1 * b0.z; acc[1][3] += a1 * b0.w;
                acc[1][4] += a1 * b1.x; acc[1][5] += a1 * b1.y; acc[1][6] += a1 * b1.z; acc[1][7] += a1 * b1.w;
                acc[2][0] += a2 * b0.x; acc[2][1] += a2 * b0.y; acc[2][2] += a2 * b0.z; acc[2][3] += a2 * b0.w;
                acc[2][4] += a2 * b1.x; acc[2][5] += a2 * b1.y; acc[2][6] += a2 * b1.z; acc[2][7] += a2 * b1.w;
            }
            __syncthreads();
        }
    }
    float* Cbase = Cpart + (size_t)sp * 48 * Nstride + n0;
#pragma unroll
    for (int i = 0; i < 3; i++) {
        float* cp = Cbase + (size_t)(ty * 3 + i) * Nstride + tx * 8;
        *(float4*)cp       = make_float4(acc[i][0], acc[i][1], acc[i][2], acc[i][3]);
        *(float4*)(cp + 4) = make_float4(acc[i][4], acc[i][5], acc[i][6], acc[i][7]);
    }
}

// ------------------------------ LSTM pointwise ------------------------------
// grid 192 x 256
__global__ void lstm_point(int layer, const float* __restrict__ bih,
                           const float* __restrict__ bhh) {
    int idx = blockIdx.x * 256 + threadIdx.x;
    int bk = idx >> 10, n = idx & 1023;
    float iv = 0.f, fv = 0.f, gv = 0.f, ov = 0.f;
#pragma unroll
    for (int p = 0; p < SPL; p++) {
        const float* r = g_gatesP + ((size_t)p * BKx + bk) * 4096;
        iv += r[n]; fv += r[n + 1024]; gv += r[n + 2048]; ov += r[n + 3072];
    }
    iv += bih[n]        + bhh[n];
    fv += bih[n + 1024] + bhh[n + 1024];
    gv += bih[n + 2048] + bhh[n + 2048];
    ov += bih[n + 3072] + bhh[n + 3072];
    size_t off = ((size_t)layer * BKx + bk) * Hx + n;
    float cp = g_c[off];
    float cn = sigf(fv) * cp + sigf(iv) * tanhf(gv);
    float hn = sigf(ov) * tanhf(cn);
    g_cs[off] = cn;
    g_hs[off] = hn;
}

// ------------------------------ attention -----------------------------------
// grid (B=16, NH=4), 256 threads. Handles all 3 beams of the batch.
__global__ void attn_kernel(const float* __restrict__ bq) {
    const int b = blockIdx.x, h = blockIdx.y, tid = threadIdx.x;
    __shared__ float q[3][256];
    __shared__ float att[3][512];
    __shared__ float red[8];
    __shared__ float inv[3];

    for (int e = tid; e < 3 * 256; e += 256) {
        int kb = e >> 8, d = e & 255;
        int col = h * 256 + d, row = b * 3 + kb;
        float v = bq[col];
#pragma unroll
        for (int p = 0; p < SPQ; p++) v += g_qP[((size_t)p * BKx + row) * Hx + col];
        q[kb][d] = v;
    }
    __syncthreads();

    const float* kbase = g_kT + ((size_t)(b * NHx + h) * DHx) * Sx;
#pragma unroll
    for (int r = 0; r < 2; r++) {
        int s = tid + r * 256;
        float a0 = 0.f, a1 = 0.f, a2 = 0.f;
#pragma unroll 4
        for (int d = 0; d < 256; d++) {
            float kv = kbase[(size_t)d * Sx + s];
            a0 += q[0][d] * kv; a1 += q[1][d] * kv; a2 += q[2][d] * kv;
        }
        const float sc = 1.0f / 16.0f;  // 1/sqrt(256)
        att[0][s] = a0 * sc; att[1][s] = a1 * sc; att[2][s] = a2 * sc;
    }
    __syncthreads();

#pragma unroll
    for (int kb = 0; kb < 3; kb++) {
        float m = fmaxf(att[kb][tid], att[kb][tid + 256]);
        m = blockMax(m, red, tid);
        float e0 = expf(att[kb][tid] - m);
        float e1 = expf(att[kb][tid + 256] - m);
        att[kb][tid] = e0; att[kb][tid + 256] = e1;
        __syncthreads();
        float s = blockSum(e0 + e1, red, tid);
        if (tid == 0) inv[kb] = 1.0f / s;
    }
    __syncthreads();

    const int d = tid;
    const float* vbase = g_vv + ((size_t)(b * NHx + h) * Sx) * DHx + d;
    float c0 = 0.f, c1 = 0.f, c2 = 0.f;
#pragma unroll 4
    for (int s = 0; s < Sx; s++) {
        float v = vbase[(size_t)s * DHx];
        c0 += att[0][s] * v; c1 += att[1][s] * v; c2 += att[2][s] * v;
    }
    g_ctx[(size_t)(b * 3 + 0) * Hx + h * 256 + d] = c0 * inv[0];
    g_ctx[(size_t)(b * 3 + 1) * Hx + h * 256 + d] = c1 * inv[1];
    g_ctx[(size_t)(b * 3 + 2) * Hx + h * 256 + d] = c2 * inv[2];
}

// ------------------------------ layernorms ----------------------------------
__global__ void ln1_kernel(const float* __restrict__ g1, const float* __restrict__ b1) {
    const int bk = blockIdx.x, tid = threadIdx.x;
    __shared__ float y[Hx];
    __shared__ float red[8];
    float loc = 0.f;
#pragma unroll
    for (int j = 0; j < 4; j++) {
        int n = tid + j * 256;
        float v = g_ctx[(size_t)bk * Hx + n] + g_hs[((size_t)1 * BKx + bk) * Hx + n];
        y[n] = v; loc += v;
    }
    float mean = blockSum(loc, red, tid) * (1.0f / Hx);
    float loc2 = 0.f;
#pragma unroll
    for (int j = 0; j < 4; j++) {
        int n = tid + j * 256;
        float d = y[n] - mean; loc2 += d * d;
    }
    float var = blockSum(loc2, red, tid) * (1.0f / Hx);
    float w = rsqrtf(var + 1e-5f);
#pragma unroll
    for (int j = 0; j < 4; j++) {
        int n = tid + j * 256;
        g_out1[(size_t)bk * Hx + n] = (y[n] - mean) * w * g1[n] + b1[n];
    }
}

__global__ void ln2tanh_kernel(const float* __restrict__ bp,
                               const float* __restrict__ g2, const float* __restrict__ b2) {
    const int bk = blockIdx.x, tid = threadIdx.x;
    __shared__ float y[Hx];
    __shared__ float red[8];
    float loc = 0.f;
#pragma unroll
    for (int j = 0; j < 4; j++) {
        int n = tid + j * 256;
        float v = bp[n] + g_out1[(size_t)bk * Hx + n];
#pragma unroll
        for (int p = 0; p < SPQ; p++) v += g_pP[((size_t)p * BKx + bk) * Hx + n];
        y[n] = v; loc += v;
    }
    float mean = blockSum(loc, red, tid) * (1.0f / Hx);
    float loc2 = 0.f;
#pragma unroll
    for (int j = 0; j < 4; j++) {
        int n = tid + j * 256;
        float d = y[n] - mean; loc2 += d * d;
    }
    float var = blockSum(loc2, red, tid) * (1.0f / Hx);
    float w = rsqrtf(var + 1e-5f);
#pragma unroll
    for (int j = 0; j < 4; j++) {
        int n = tid + j * 256;
        g_tanh[(size_t)bk * Hx + n] = tanhf((y[n] - mean) * w * g2[n] + b2[n]);
    }
}

// ------------------------------ log-softmax + output ------------------------
__global__ void lsm_kernel(float* __restrict__ out, int step) {
    const int bk = blockIdx.x, tid = threadIdx.x;
    __shared__ float sl[Cx];
    __shared__ float red[8];
    float m = -INFINITY;
    for (int c = tid; c < Cx; c += 256) {
        float v = 0.f;
#pragma unroll
        for (int p = 0; p < SPG; p++) v += g_gP[((size_t)p * BKx + bk) * 2048 + c];
        sl[c] = v;
        m = fmaxf(m, v);
    }
    float M = blockMax(m, red, tid);
    float s = 0.f;
    for (int c = tid; c < Cx; c += 256) s += expf(sl[c] - M);
    float S = blockSum(s, red, tid);
    float lse = logf(S);
    float sc = g_score[bk];
    for (int c = tid; c < Cx; c += 256) {
        float lp = sl[c] - M - lse;
        out[((size_t)step * BKx + bk) * Cx + c] = lp;
        g_cand[(size_t)bk * Cx + c] = sc + lp;
    }
}

// ------------------------------ top-k + beam update -------------------------
// grid 16 (batch), 256 threads. lax.top_k semantics: ties -> lowest index.
__global__ void topk_kernel() {
    const int b = blockIdx.x, tid = threadIdx.x;
    __shared__ float rv[8];
    __shared__ int ri[8];
    __shared__ int chI[3];
    __shared__ float chV[3];

    for (int r = 0; r < 3; r++) {
        float bv = -INFINITY;
        int bi = 0x7fffffff;
        for (int j = tid; j < Kb * Cx; j += 256) {
            if (r > 0 && j == chI[0]) continue;
            if (r > 1 && j == chI[1]) continue;
            float v = g_cand[(size_t)(b * Kb + j / Cx) * Cx + (j % Cx)];
            if (v > bv || (v == bv && j < bi)) { bv = v; bi = j; }
        }
#pragma unroll
        for (int o = 16; o; o >>= 1) {
            float ov = __shfl_xor_sync(0xffffffffu, bv, o);
            int oi = __shfl_xor_sync(0xffffffffu, bi, o);
            if (ov > bv || (ov == bv && oi < bi)) { bv = ov; bi = oi; }
        }
        if ((tid & 31) == 0) { rv[tid >> 5] = bv; ri[tid >> 5] = bi; }
        __syncthreads();
        if (tid == 0) {
            float fv = rv[0]; int fi = ri[0];
#pragma unroll
            for (int w = 1; w < 8; w++) {
                if (rv[w] > fv || (rv[w] == fv && ri[w] < fi)) { fv = rv[w]; fi = ri[w]; }
            }
            chI[r] = fi; chV[r] = fv;
        }
        __syncthreads();
    }
    if (tid < 3) {
        int j = chI[tid];
        float v = chV[tid];
        int sym = j % Cx;
        int src = b * Kb + j / Cx;
        g_inp[b * Kb + tid] = sym;
        g_pred[b * Kb + tid] = src;
        g_score[b * Kb + tid] = (sym == EOSv) ? NEGV : v;
    }
}

// ------------------------------ state gather --------------------------------
// grid (48, 2), 256 threads
__global__ void gather_kernel() {
    const int bk = blockIdx.x, l = blockIdx.y, tid = threadIdx.x;
    const int src = g_pred[bk];
    size_t dst = ((size_t)l * BKx + bk) * Hx;
    size_t so  = ((size_t)l * BKx + src) * Hx;
#pragma unroll
    for (int j = 0; j < 4; j++) {
        int n = tid + j * 256;
        g_h[dst + n] = g_hs[so + n];
        g_c[dst + n] = g_cs[so + n];
    }
}

// ------------------------------ host launcher -------------------------------
extern "C" void kernel_launch(void* const* d_in, const int* in_sizes, int n_in,
                              void* d_out, int out_size) {
    const float* enc  = (const float*)d_in[0];
    const float* emb  = (const float*)d_in[1];
    const float* w_ih = (const float*)d_in[2];
    const float* w_hh = (const float*)d_in[3];
    const float* b_ih = (const float*)d_in[4];
    const float* b_hh = (const float*)d_in[5];
    const float* wq   = (const float*)d_in[6];
    const float* bq   = (const float*)d_in[7];
    const float* wk   = (const float*)d_in[8];
    const float* bk_  = (const float*)d_in[9];
    const float* wv   = (const float*)d_in[10];
    const float* bv   = (const float*)d_in[11];
    const float* ln1g = (const float*)d_in[12];
    const float* ln1b = (const float*)d_in[13];
    const float* wp   = (const float*)d_in[14];
    const float* bp   = (const float*)d_in[15];
    const float* ln2g = (const float*)d_in[16];
    const float* ln2b = (const float*)d_in[17];
    const float* wg   = (const float*)d_in[18];
    float* out = (float*)d_out;

    // device-global addresses (cudaGetSymbolAddress is capture-safe: no stream op)
    float *p_h, *p_hs, *p_out1, *p_tanh, *p_gatesP, *p_qP, *p_pP, *p_gP;
    int* p_inp;
    cudaGetSymbolAddress((void**)&p_h, g_h);
    cudaGetSymbolAddress((void**)&p_hs, g_hs);
    cudaGetSymbolAddress((void**)&p_out1, g_out1);
    cudaGetSymbolAddress((void**)&p_tanh, g_tanh);
    cudaGetSymbolAddress((void**)&p_gatesP, g_gatesP);
    cudaGetSymbolAddress((void**)&p_qP, g_qP);
    cudaGetSymbolAddress((void**)&p_pP, g_pP);
    cudaGetSymbolAddress((void**)&p_gP, g_gP);
    cudaGetSymbolAddress((void**)&p_inp, g_inp);

    init_kernel<<<384, 256>>>();
    kvproj_kernel<<<dim3(16, 128, 2), 256>>>(enc, wk, bk_, wv, bv);

    const size_t WL = (size_t)4096 * Hx;  // per-layer weight size

    for (int t = 0; t < Tx; t++) {
        // LSTM layer 0: A0 = embedding[inp], A1 = h[0]
        gemm48<true><<<dim3(32, SPL), 256>>>(emb, p_inp, w_ih,
                                             p_h, w_hh,
                                             Hx, Hx / SPL, 4096, 4096, p_gatesP);
        lstm_point<<<192, 256>>>(0, b_ih, b_hh);
        // LSTM layer 1: A0 = h_stage[0], A1 = h[1]
        gemm48<true><<<dim3(32, SPL), 256>>>(p_hs, nullptr, w_ih + WL,
                                             p_h + BKx * Hx, w_hh + WL,
                                             Hx, Hx / SPL, 4096, 4096, p_gatesP);
        lstm_point<<<192, 256>>>(1, b_ih + 4096, b_hh + 4096);
        // q projection
        gemm48<false><<<dim3(8, SPQ), 256>>>(p_hs + BKx * Hx, nullptr, wq,
                                             nullptr, nullptr,
                                             Hx, Hx / SPQ, Hx, Hx, p_qP);
        attn_kernel<<<dim3(16, 4), 256>>>(bq);
        ln1_kernel<<<48, 256>>>(ln1g, ln1b);
        // p projection
        gemm48<false><<<dim3(8, SPQ), 256>>>(p_out1, nullptr, wp,
                                             nullptr, nullptr,
                                             Hx, Hx / SPQ, Hx, Hx, p_pP);
        ln2tanh_kernel<<<48, 256>>>(bp, ln2g, ln2b);
        // wg projection
        gemm48<false><<<dim3(16, SPG), 256>>>(p_tanh, nullptr, wg,
                                              nullptr, nullptr,
                                              Hx, Hx / SPG, Cx, 2048, p_gP);
        lsm_kernel<<<48, 256>>>(out, t);
        topk_kernel<<<16, 256>>>();
        gather_kernel<<<dim3(48, 2), 256>>>();
    }
    (void)in_sizes; (void)n_in; (void)out_size;
}

// round 4
// speedup vs baseline: 1.2300x; 1.2300x over previous
#include <cuda_runtime.h>
#include <math.h>
#include <stdint.h>
#include <stddef.h>

// ---------------------------------------------------------------------------
// SpeechTopKDecoder: T=64-step beam-search decoder. fp32 throughout.
// Deterministic: fixed-order split-K reductions, no float atomics.
// R4: fix gemm_kn B-loader coverage (was filling only half the 256-wide tile).
// ---------------------------------------------------------------------------

#define Bb   16
#define Kb   3
#define Sx   512
#define Hx   1024
#define Cx   2000
#define Tx   64
#define NHx  4
#define DHx  256
#define BKx  48
#define NEGV (-1000000000.0f)
#define SOSv 1
#define EOSv 2

#define SPL 8    // lstm split-K
#define SPQ 32   // q / p split-K
#define SPG 16   // wg split-K

// ------------------------------ device scratch ------------------------------
__device__ float g_kT [(size_t)Bb * NHx * DHx * Sx];   // keys   (B,NH,DH,S)
__device__ float g_vv [(size_t)Bb * NHx * Sx * DHx];   // values (B,NH,S,DH)
__device__ float g_h  [2 * BKx * Hx];
__device__ float g_c  [2 * BKx * Hx];
__device__ float g_hs [2 * BKx * Hx];
__device__ float g_cs [2 * BKx * Hx];
__device__ float g_gatesP[(size_t)SPL * BKx * 4096];
__device__ float g_qP [(size_t)SPQ * BKx * Hx];
__device__ float g_pP [(size_t)SPQ * BKx * Hx];
__device__ float g_gP [(size_t)SPG * BKx * 2048];
__device__ float g_ctx [BKx * Hx];
__device__ float g_out1[BKx * Hx];
__device__ float g_tanh[BKx * Hx];
__device__ float g_cand[BKx * Cx];
__device__ float g_score[BKx];
__device__ int   g_inp [BKx];
__device__ int   g_pred[BKx];

// ------------------------------ reductions ----------------------------------
__device__ __forceinline__ float warpMax(float v) {
#pragma unroll
    for (int o = 16; o; o >>= 1) v = fmaxf(v, __shfl_xor_sync(0xffffffffu, v, o));
    return v;
}
__device__ __forceinline__ float warpSum(float v) {
#pragma unroll
    for (int o = 16; o; o >>= 1) v += __shfl_xor_sync(0xffffffffu, v, o);
    return v;
}
__device__ __forceinline__ float blockMax(float v, float* red, int tid) {
    v = warpMax(v);
    if ((tid & 31) == 0) red[tid >> 5] = v;
    __syncthreads();
    float r = red[0];
#pragma unroll
    for (int w = 1; w < 8; w++) r = fmaxf(r, red[w]);
    __syncthreads();
    return r;
}
__device__ __forceinline__ float blockSum(float v, float* red, int tid) {
    v = warpSum(v);
    if ((tid & 31) == 0) red[tid >> 5] = v;
    __syncthreads();
    float r = red[0];
#pragma unroll
    for (int w = 1; w < 8; w++) r += red[w];
    __syncthreads();
    return r;
}
__device__ __forceinline__ float sigf(float x) { return 1.0f / (1.0f + expf(-x)); }

// ------------------------------ init ----------------------------------------
__global__ void init_kernel() {
    int idx = blockIdx.x * 256 + threadIdx.x;
    if (idx < 2 * BKx * Hx) { g_h[idx] = 0.0f; g_c[idx] = 0.0f; }
    if (idx < BKx) {
        g_score[idx] = (idx % Kb == 0) ? 0.0f : NEGV;
        g_inp[idx] = SOSv;
    }
}

// ------------------------------ K/V projection ------------------------------
// 128x128 tiles, 256 threads, 8x8 per thread. grid (8 n-tiles, 64 m-tiles).
__global__ void __launch_bounds__(256)
kvproj_kernel(const float* __restrict__ enc, const float* __restrict__ W,
              const float* __restrict__ bias, int z) {
    __shared__ float As[16][132];   // As[kk][m]
    __shared__ float Bs[16][132];   // Bs[kk][n]
    const int tid = threadIdx.x;
    const int tx = tid & 15, ty = tid >> 4;
    const int n0 = blockIdx.x * 128;
    const int m0 = blockIdx.y * 128;

    const int ak4 = tid & 3,  am = tid >> 2;   // A loader: 2 reps of 64 rows
    const int bn4 = tid & 31, bkk = tid >> 5;  // B loader: 2 reps of 8 kk

    float4 aR[2], bR[2];
    float acc[8][8];
#pragma unroll
    for (int i = 0; i < 8; i++)
#pragma unroll
        for (int j = 0; j < 8; j++) acc[i][j] = 0.0f;

#define KV_LOAD(kb)                                                            \
    {                                                                          \
        aR[0] = *(const float4*)(enc + (size_t)(m0 + am) * Hx + (kb) + ak4*4); \
        aR[1] = *(const float4*)(enc + (size_t)(m0 + 64 + am) * Hx + (kb) + ak4*4); \
        bR[0] = *(const float4*)(W + (size_t)((kb) + bkk) * Hx + n0 + bn4*4);  \
        bR[1] = *(const float4*)(W + (size_t)((kb) + 8 + bkk) * Hx + n0 + bn4*4); \
    }
#define KV_STORE()                                                             \
    {                                                                          \
        float av0[4] = {aR[0].x, aR[0].y, aR[0].z, aR[0].w};                   \
        float av1[4] = {aR[1].x, aR[1].y, aR[1].z, aR[1].w};                   \
        _Pragma("unroll")                                                      \
        for (int j = 0; j < 4; j++) {                                          \
            As[ak4*4 + j][am]      = av0[j];                                   \
            As[ak4*4 + j][64 + am] = av1[j];                                   \
        }                                                                      \
        *(float4*)&Bs[bkk][bn4*4]     = bR[0];                                 \
        *(float4*)&Bs[8 + bkk][bn4*4] = bR[1];                                 \
    }

    KV_LOAD(0);
#pragma unroll 1
    for (int t = 0; t < Hx / 16; t++) {
        __syncthreads();
        KV_STORE();
        __syncthreads();
        if (t + 1 < Hx / 16) KV_LOAD((t + 1) * 16);
#pragma unroll 2
        for (int kk = 0; kk < 16; kk++) {
            float a[8], b[8];
#pragma unroll
            for (int r = 0; r < 8; r++) a[r] = As[kk][ty + 16 * r];
#pragma unroll
            for (int k = 0; k < 8; k++) b[k] = Bs[kk][tx + 16 * k];
#pragma unroll
            for (int r = 0; r < 8; r++)
#pragma unroll
                for (int k = 0; k < 8; k++) acc[r][k] = fmaf(a[r], b[k], acc[r][k]);
        }
    }

#pragma unroll
    for (int r = 0; r < 8; r++) {
        int gm = m0 + ty + 16 * r;
        int b = gm >> 9, s = gm & 511;
#pragma unroll
        for (int k = 0; k < 8; k++) {
            int col = n0 + tx + 16 * k;
            int h = col >> 8, d = col & 255;
            float v = acc[r][k] + bias[col];
            if (z == 0)
                g_kT[(((size_t)b * NHx + h) * DHx + d) * Sx + s] = v;
            else
                g_vv[(((size_t)b * NHx + h) * Sx + s) * DHx + d] = v;
        }
    }
#undef KV_LOAD
#undef KV_STORE
}

// ------------------------------ LSTM GEMM -----------------------------------
// 48x256 tile, 256 threads, 6x8/thread. B is (N=4096, K=1024) row-major (two
// pairs: w_ih + w_hh). Bs stored n-major [256][33] (transpose-free from NK).
__global__ void __launch_bounds__(256)
gemm_lstm(const float* __restrict__ A0, const int* __restrict__ aidx,
          const float* __restrict__ B0,
          const float* __restrict__ A1, const float* __restrict__ B1,
          int kPerSplit, float* __restrict__ Cpart) {
    __shared__ float As[32][49];    // As[kk][m]
    __shared__ float Bs[256][33];   // Bs[n][kk]
    __shared__ int sIdx[48];

    const int tid = threadIdx.x;
    const int tx = tid & 31, ty = tid >> 5;
    const int n0 = blockIdx.x * 256;
    const int sp = blockIdx.y;
    const int k0 = sp * kPerSplit;

    if (aidx != nullptr && tid < 48) sIdx[tid] = aidx[tid];

    const int bk4 = tid & 7;   // k-group 0..7
    const int bn  = tid >> 3;  // 0..31

    const int tilesPerPair = kPerSplit >> 5;
    const int ntiles = tilesPerPair * 2;

    float4 bR[8];
    float4 aR[2];
    float acc[6][8];
#pragma unroll
    for (int i = 0; i < 6; i++)
#pragma unroll
        for (int j = 0; j < 8; j++) acc[i][j] = 0.0f;

    __syncthreads();  // sIdx visible

#define LS_LOAD(t)                                                             \
    {                                                                          \
        int pair = (t) / tilesPerPair;                                         \
        int kb = k0 + ((t) - pair * tilesPerPair) * 32;                        \
        const float* A = pair ? A1 : A0;                                       \
        const float* B = pair ? B1 : B0;                                       \
        bool gat = (pair == 0) && (aidx != nullptr);                           \
        _Pragma("unroll")                                                      \
        for (int r = 0; r < 8; r++)                                            \
            bR[r] = *(const float4*)(B + (size_t)(n0 + bn + 32*r) * Hx + kb + bk4*4); \
        int r0 = gat ? sIdx[bn] : bn;                                          \
        aR[0] = *(const float4*)(A + (size_t)r0 * Hx + kb + bk4*4);            \
        if (bn < 16) {                                                         \
            int r1 = gat ? sIdx[32 + bn] : (32 + bn);                          \
            aR[1] = *(const float4*)(A + (size_t)r1 * Hx + kb + bk4*4);        \
        }                                                                      \
    }
#define LS_STORE()                                                             \
    {                                                                          \
        _Pragma("unroll")                                                      \
        for (int r = 0; r < 8; r++) {                                          \
            float bv[4] = {bR[r].x, bR[r].y, bR[r].z, bR[r].w};                \
            _Pragma("unroll")                                                  \
            for (int j = 0; j < 4; j++) Bs[bn + 32*r][bk4*4 + j] = bv[j];      \
        }                                                                      \
        float av0[4] = {aR[0].x, aR[0].y, aR[0].z, aR[0].w};                   \
        _Pragma("unroll")                                                      \
        for (int j = 0; j < 4; j++) As[bk4*4 + j][bn] = av0[j];                \
        if (bn < 16) {                                                         \
            float av1[4] = {aR[1].x, aR[1].y, aR[1].z, aR[1].w};               \
            _Pragma("unroll")                                                  \
            for (int j = 0; j < 4; j++) As[bk4*4 + j][32 + bn] = av1[j];       \
        }                                                                      \
    }

    LS_LOAD(0);
#pragma unroll 1
    for (int t = 0; t < ntiles; t++) {
        __syncthreads();
        LS_STORE();
        __syncthreads();
        if (t + 1 < ntiles) LS_LOAD(t + 1);
#pragma unroll 4
        for (int kk = 0; kk < 32; kk++) {
            float a[6];
#pragma unroll
            for (int r = 0; r < 6; r++) a[r] = As[kk][ty * 6 + r];
#pragma unroll
            for (int k = 0; k < 8; k++) {
                float b = Bs[tx + 32 * k][kk];
#pragma unroll
                for (int r = 0; r < 6; r++) acc[r][k] = fmaf(a[r], b, acc[r][k]);
            }
        }
    }

    float* Cb = Cpart + ((size_t)sp * 48 + ty * 6) * 4096 + n0 + tx;
#pragma unroll
    for (int r = 0; r < 6; r++)
#pragma unroll
        for (int k = 0; k < 8; k++) Cb[(size_t)r * 4096 + 32 * k] = acc[r][k];
#undef LS_LOAD
#undef LS_STORE
}

// ------------------------------ KN GEMM (q/p/wg) ----------------------------
// 48x256 tile, 256 threads, 6x8/thread. B is (K=1024, N) row-major.
// Bs stored kk-major [32][264]. Loader: bn4 covers 64*4=256 cols, bkk+4r
// covers 32 kk rows -> full 32x256 tile (fix for R3's half-filled tile).
__global__ void __launch_bounds__(256)
gemm_kn(const float* __restrict__ A, const float* __restrict__ B,
        int kPerSplit, int Nreal, int Nstride, float* __restrict__ Cpart) {
    __shared__ float As[32][49];    // As[kk][m]
    __shared__ float Bs[32][264];   // Bs[kk][n]

    const int tid = threadIdx.x;
    const int tx = tid & 31, ty = tid >> 5;
    const int n0 = blockIdx.x * 256;
    const int sp = blockIdx.y;
    const int k0 = sp * kPerSplit;

    const int ak4 = tid & 7, am = tid >> 3;    // A loader
    const int bn4 = tid & 63, bkk = tid >> 6;  // B loader: 8 reps, kk = bkk+4r

    const int ntiles = kPerSplit >> 5;

    float4 bR[8];
    float4 aR[2];
    float acc[6][8];
#pragma unroll
    for (int i = 0; i < 6; i++)
#pragma unroll
        for (int j = 0; j < 8; j++) acc[i][j] = 0.0f;

#define KN_LOAD(kb)                                                            \
    {                                                                          \
        int col = n0 + bn4 * 4;                                                \
        _Pragma("unroll")                                                      \
        for (int r = 0; r < 8; r++) {                                          \
            bR[r] = (col < Nreal)                                              \
                ? *(const float4*)(B + (size_t)((kb) + bkk + 4*r) * Nreal + col) \
                : make_float4(0.f, 0.f, 0.f, 0.f);                             \
        }                                                                      \
        aR[0] = *(const float4*)(A + (size_t)am * Hx + (kb) + ak4*4);          \
        if (am < 16)                                                           \
            aR[1] = *(const float4*)(A + (size_t)(32 + am) * Hx + (kb) + ak4*4); \
    }
#define KN_STORE()                                                             \
    {                                                                          \
        _Pragma("unroll")                                                      \
        for (int r = 0; r < 8; r++) *(float4*)&Bs[bkk + 4*r][bn4*4] = bR[r];   \
        float av0[4] = {aR[0].x, aR[0].y, aR[0].z, aR[0].w};                   \
        _Pragma("unroll")                                                      \
        for (int j = 0; j < 4; j++) As[ak4*4 + j][am] = av0[j];                \
        if (am < 16) {                                                         \
            float av1[4] = {aR[1].x, aR[1].y, aR[1].z, aR[1].w};               \
            _Pragma("unroll")                                                  \
            for (int j = 0; j < 4; j++) As[ak4*4 + j][32 + am] = av1[j];       \
        }                                                                      \
    }

    KN_LOAD(k0);
#pragma unroll 1
    for (int t = 0; t < ntiles; t++) {
        __syncthreads();
        KN_STORE();
        __syncthreads();
        if (t + 1 < ntiles) KN_LOAD(k0 + (t + 1) * 32);
#pragma unroll 4
        for (int kk = 0; kk < 32; kk++) {
            float a[6];
#pragma unroll
            for (int r = 0; r < 6; r++) a[r] = As[kk][ty * 6 + r];
#pragma unroll
            for (int k = 0; k < 8; k++) {
                float b = Bs[kk][tx + 32 * k];
#pragma unroll
                for (int r = 0; r < 6; r++) acc[r][k] = fmaf(a[r], b, acc[r][k]);
            }
        }
    }

    float* Cb = Cpart + ((size_t)sp * 48 + ty * 6) * Nstride + n0 + tx;
#pragma unroll
    for (int r = 0; r < 6; r++)
#pragma unroll
        for (int k = 0; k < 8; k++) Cb[(size_t)r * Nstride + 32 * k] = acc[r][k];
#undef KN_LOAD
#undef KN_STORE
}

// ------------------------------ LSTM pointwise ------------------------------
__global__ void lstm_point(int layer, const float* __restrict__ bih,
                           const float* __restrict__ bhh) {
    int idx = blockIdx.x * 256 + threadIdx.x;
    int bk = idx >> 10, n = idx & 1023;
    float iv = 0.f, fv = 0.f, gv = 0.f, ov = 0.f;
#pragma unroll
    for (int p = 0; p < SPL; p++) {
        const float* r = g_gatesP + ((size_t)p * BKx + bk) * 4096;
        iv += r[n]; fv += r[n + 1024]; gv += r[n + 2048]; ov += r[n + 3072];
    }
    iv += bih[n]        + bhh[n];
    fv += bih[n + 1024] + bhh[n + 1024];
    gv += bih[n + 2048] + bhh[n + 2048];
    ov += bih[n + 3072] + bhh[n + 3072];
    size_t off = ((size_t)layer * BKx + bk) * Hx + n;
    float cp = g_c[off];
    float cn = sigf(fv) * cp + sigf(iv) * tanhf(gv);
    float hn = sigf(ov) * tanhf(cn);
    g_cs[off] = cn;
    g_hs[off] = hn;
}

// ------------------------------ attention -----------------------------------
__global__ void attn_kernel(const float* __restrict__ bq) {
    const int b = blockIdx.x, h = blockIdx.y, tid = threadIdx.x;
    __shared__ float q[3][256];
    __shared__ float att[3][512];
    __shared__ float red[8];
    __shared__ float inv[3];

    for (int e = tid; e < 3 * 256; e += 256) {
        int kb = e >> 8, d = e & 255;
        int col = h * 256 + d, row = b * 3 + kb;
        float v = bq[col];
#pragma unroll
        for (int p = 0; p < SPQ; p++) v += g_qP[((size_t)p * BKx + row) * Hx + col];
        q[kb][d] = v;
    }
    __syncthreads();

    const float* kbase = g_kT + ((size_t)(b * NHx + h) * DHx) * Sx;
#pragma unroll
    for (int r = 0; r < 2; r++) {
        int s = tid + r * 256;
        float a0 = 0.f, a1 = 0.f, a2 = 0.f;
#pragma unroll 4
        for (int d = 0; d < 256; d++) {
            float kv = kbase[(size_t)d * Sx + s];
            a0 += q[0][d] * kv; a1 += q[1][d] * kv; a2 += q[2][d] * kv;
        }
        const float sc = 1.0f / 16.0f;
        att[0][s] = a0 * sc; att[1][s] = a1 * sc; att[2][s] = a2 * sc;
    }
    __syncthreads();

#pragma unroll
    for (int kb = 0; kb < 3; kb++) {
        float m = fmaxf(att[kb][tid], att[kb][tid + 256]);
        m = blockMax(m, red, tid);
        float e0 = expf(att[kb][tid] - m);
        float e1 = expf(att[kb][tid + 256] - m);
        att[kb][tid] = e0; att[kb][tid + 256] = e1;
        __syncthreads();
        float s = blockSum(e0 + e1, red, tid);
        if (tid == 0) inv[kb] = 1.0f / s;
    }
    __syncthreads();

    const int d = tid;
    const float* vbase = g_vv + ((size_t)(b * NHx + h) * Sx) * DHx + d;
    float c0 = 0.f, c1 = 0.f, c2 = 0.f;
#pragma unroll 4
    for (int s = 0; s < Sx; s++) {
        float v = vbase[(size_t)s * DHx];
        c0 += att[0][s] * v; c1 += att[1][s] * v; c2 += att[2][s] * v;
    }
    g_ctx[(size_t)(b * 3 + 0) * Hx + h * 256 + d] = c0 * inv[0];
    g_ctx[(size_t)(b * 3 + 1) * Hx + h * 256 + d] = c1 * inv[1];
    g_ctx[(size_t)(b * 3 + 2) * Hx + h * 256 + d] = c2 * inv[2];
}

// ------------------------------ layernorms ----------------------------------
__global__ void ln1_kernel(const float* __restrict__ g1, const float* __restrict__ b1) {
    const int bk = blockIdx.x, tid = threadIdx.x;
    __shared__ float y[Hx];
    __shared__ float red[8];
    float loc = 0.f;
#pragma unroll
    for (int j = 0; j < 4; j++) {
        int n = tid + j * 256;
        float v = g_ctx[(size_t)bk * Hx + n] + g_hs[((size_t)1 * BKx + bk) * Hx + n];
        y[n] = v; loc += v;
    }
    float mean = blockSum(loc, red, tid) * (1.0f / Hx);
    float loc2 = 0.f;
#pragma unroll
    for (int j = 0; j < 4; j++) {
        int n = tid + j * 256;
        float d = y[n] - mean; loc2 += d * d;
    }
    float var = blockSum(loc2, red, tid) * (1.0f / Hx);
    float w = rsqrtf(var + 1e-5f);
#pragma unroll
    for (int j = 0; j < 4; j++) {
        int n = tid + j * 256;
        g_out1[(size_t)bk * Hx + n] = (y[n] - mean) * w * g1[n] + b1[n];
    }
}

__global__ void ln2tanh_kernel(const float* __restrict__ bp,
                               const float* __restrict__ g2, const float* __restrict__ b2) {
    const int bk = blockIdx.x, tid = threadIdx.x;
    __shared__ float y[Hx];
    __shared__ float red[8];
    float loc = 0.f;
#pragma unroll
    for (int j = 0; j < 4; j++) {
        int n = tid + j * 256;
        float v = bp[n] + g_out1[(size_t)bk * Hx + n];
#pragma unroll
        for (int p = 0; p < SPQ; p++) v += g_pP[((size_t)p * BKx + bk) * Hx + n];
        y[n] = v; loc += v;
    }
    float mean = blockSum(loc, red, tid) * (1.0f / Hx);
    float loc2 = 0.f;
#pragma unroll
    for (int j = 0; j < 4; j++) {
        int n = tid + j * 256;
        float d = y[n] - mean; loc2 += d * d;
    }
    float var = blockSum(loc2, red, tid) * (1.0f / Hx);
    float w = rsqrtf(var + 1e-5f);
#pragma unroll
    for (int j = 0; j < 4; j++) {
        int n = tid + j * 256;
        g_tanh[(size_t)bk * Hx + n] = tanhf((y[n] - mean) * w * g2[n] + b2[n]);
    }
}

// ------------------------------ log-softmax + output ------------------------
__global__ void lsm_kernel(float* __restrict__ out, int step) {
    const int bk = blockIdx.x, tid = threadIdx.x;
    __shared__ float sl[Cx];
    __shared__ float red[8];
    float m = -INFINITY;
    for (int c = tid; c < Cx; c += 256) {
        float v = 0.f;
#pragma unroll
        for (int p = 0; p < SPG; p++) v += g_gP[((size_t)p * BKx + bk) * 2048 + c];
        sl[c] = v;
        m = fmaxf(m, v);
    }
    float M = blockMax(m, red, tid);
    float s = 0.f;
    for (int c = tid; c < Cx; c += 256) s += expf(sl[c] - M);
    float S = blockSum(s, red, tid);
    float lse = logf(S);
    float sc = g_score[bk];
    for (int c = tid; c < Cx; c += 256) {
        float lp = sl[c] - M - lse;
        out[((size_t)step * BKx + bk) * Cx + c] = lp;
        g_cand[(size_t)bk * Cx + c] = sc + lp;
    }
}

// ------------------------------ top-k + beam update -------------------------
__global__ void topk_kernel() {
    const int b = blockIdx.x, tid = threadIdx.x;
    __shared__ float rv[8];
    __shared__ int ri[8];
    __shared__ int chI[3];
    __shared__ float chV[3];

    for (int r = 0; r < 3; r++) {
        float bv = -INFINITY;
        int bi = 0x7fffffff;
        for (int j = tid; j < Kb * Cx; j += 256) {
            if (r > 0 && j == chI[0]) continue;
            if (r > 1 && j == chI[1]) continue;
            float v = g_cand[(size_t)(b * Kb + j / Cx) * Cx + (j % Cx)];
            if (v > bv || (v == bv && j < bi)) { bv = v; bi = j; }
        }
#pragma unroll
        for (int o = 16; o; o >>= 1) {
            float ov = __shfl_xor_sync(0xffffffffu, bv, o);
            int oi = __shfl_xor_sync(0xffffffffu, bi, o);
            if (ov > bv || (ov == bv && oi < bi)) { bv = ov; bi = oi; }
        }
        if ((tid & 31) == 0) { rv[tid >> 5] = bv; ri[tid >> 5] = bi; }
        __syncthreads();
        if (tid == 0) {
            float fv = rv[0]; int fi = ri[0];
#pragma unroll
            for (int w = 1; w < 8; w++) {
                if (rv[w] > fv || (rv[w] == fv && ri[w] < fi)) { fv = rv[w]; fi = ri[w]; }
            }
            chI[r] = fi; chV[r] = fv;
        }
        __syncthreads();
    }
    if (tid < 3) {
        int j = chI[tid];
        float v = chV[tid];
        int sym = j % Cx;
        int src = b * Kb + j / Cx;
        g_inp[b * Kb + tid] = sym;
        g_pred[b * Kb + tid] = src;
        g_score[b * Kb + tid] = (sym == EOSv) ? NEGV : v;
    }
}

// ------------------------------ state gather --------------------------------
__global__ void gather_kernel() {
    const int bk = blockIdx.x, l = blockIdx.y, tid = threadIdx.x;
    const int src = g_pred[bk];
    size_t dst = ((size_t)l * BKx + bk) * Hx;
    size_t so  = ((size_t)l * BKx + src) * Hx;
#pragma unroll
    for (int j = 0; j < 4; j++) {
        int n = tid + j * 256;
        g_h[dst + n] = g_hs[so + n];
        g_c[dst + n] = g_cs[so + n];
    }
}

// ------------------------------ host launcher -------------------------------
extern "C" void kernel_launch(void* const* d_in, const int* in_sizes, int n_in,
                              void* d_out, int out_size) {
    const float* enc  = (const float*)d_in[0];
    const float* emb  = (const float*)d_in[1];
    const float* w_ih = (const float*)d_in[2];
    const float* w_hh = (const float*)d_in[3];
    const float* b_ih = (const float*)d_in[4];
    const float* b_hh = (const float*)d_in[5];
    const float* wq   = (const float*)d_in[6];
    const float* bq   = (const float*)d_in[7];
    const float* wk   = (const float*)d_in[8];
    const float* bk_  = (const float*)d_in[9];
    const float* wv   = (const float*)d_in[10];
    const float* bv   = (const float*)d_in[11];
    const float* ln1g = (const float*)d_in[12];
    const float* ln1b = (const float*)d_in[13];
    const float* wp   = (const float*)d_in[14];
    const float* bp   = (const float*)d_in[15];
    const float* ln2g = (const float*)d_in[16];
    const float* ln2b = (const float*)d_in[17];
    const float* wg   = (const float*)d_in[18];
    float* out = (float*)d_out;

    float *p_h, *p_hs, *p_out1, *p_tanh, *p_gatesP, *p_qP, *p_pP, *p_gP;
    int* p_inp;
    cudaGetSymbolAddress((void**)&p_h, g_h);
    cudaGetSymbolAddress((void**)&p_hs, g_hs);
    cudaGetSymbolAddress((void**)&p_out1, g_out1);
    cudaGetSymbolAddress((void**)&p_tanh, g_tanh);
    cudaGetSymbolAddress((void**)&p_gatesP, g_gatesP);
    cudaGetSymbolAddress((void**)&p_qP, g_qP);
    cudaGetSymbolAddress((void**)&p_pP, g_pP);
    cudaGetSymbolAddress((void**)&p_gP, g_gP);
    cudaGetSymbolAddress((void**)&p_inp, g_inp);

    init_kernel<<<384, 256>>>();
    // two launches so ncu -s 5 -c 1 lands on gemm_lstm
    kvproj_kernel<<<dim3(8, 64), 256>>>(enc, wk, bk_, 0);
    kvproj_kernel<<<dim3(8, 64), 256>>>(enc, wv, bv, 1);

    const size_t WL = (size_t)4096 * Hx;

    for (int t = 0; t < Tx; t++) {
        gemm_lstm<<<dim3(16, SPL), 256>>>(emb, p_inp, w_ih,
                                          p_h, w_hh, Hx / SPL, p_gatesP);
        lstm_point<<<192, 256>>>(0, b_ih, b_hh);
        gemm_lstm<<<dim3(16, SPL), 256>>>(p_hs, nullptr, w_ih + WL,
                                          p_h + BKx * Hx, w_hh + WL,
                                          Hx / SPL, p_gatesP);
        lstm_point<<<192, 256>>>(1, b_ih + 4096, b_hh + 4096);
        gemm_kn<<<dim3(4, SPQ), 256>>>(p_hs + BKx * Hx, wq, Hx / SPQ, Hx, Hx, p_qP);
        attn_kernel<<<dim3(16, 4), 256>>>(bq);
        ln1_kernel<<<48, 256>>>(ln1g, ln1b);
        gemm_kn<<<dim3(4, SPQ), 256>>>(p_out1, wp, Hx / SPQ, Hx, Hx, p_pP);
        ln2tanh_kernel<<<48, 256>>>(bp, ln2g, ln2b);
        gemm_kn<<<dim3(8, SPG), 256>>>(p_tanh, wg, Hx / SPG, Cx, 2048, p_gP);
        lsm_kernel<<<48, 256>>>(out, t);
        topk_kernel<<<16, 256>>>();
        gather_kernel<<<dim3(48, 2), 256>>>();
    }
    (void)in_sizes; (void)n_in; (void)out_size;
}